// round 1
// baseline (speedup 1.0000x reference)
#include <cuda_runtime.h>
#include <cuda_bf16.h>

// Problem constants (fixed by setup_inputs)
#define BB 32      // batch
#define TT 2048    // timesteps
#define HH 512     // hidden per direction
#define DH 1024    // D*H
#define CC 1024    // input feature size
#define CHUNKS 32  // t-chunks per batch in the fused pass
#define TC (TT / CHUNKS)  // 64 timesteps per chunk

// ---------------- scratch (no runtime allocation allowed) ----------------
__device__ float g_qpart[2][BB * DH];          // K-split partial query proj
__device__ float g_scores[BB * TT];            // raw (pre-softmax) scores
__device__ float g_pm[BB * CHUNKS];            // per-chunk running max
__device__ float g_pl[BB * CHUNKS];            // per-chunk running sum
__device__ float g_pa[BB * CHUNKS * DH];       // per-chunk weighted accum (4 MB)
__device__ float g_M[BB];                      // global max per batch
__device__ float g_invL[BB];                   // 1/denominator per batch

// ---------------------------------------------------------------------------
// Kernel A: query projection partials.
//   q[b,d] = sum_c input[b,c] * Wq[d,c]   (bq added later in kernel B)
// grid (64, 2): 16 d's per block (8 warps x 2 d), K-split of 512 each.
// Warp-cooperative: lane covers k, 32 batch accumulators, log-depth
// multi-value shuffle reduction (31 shfl) leaves acc for b=lane in acc[0].
// ---------------------------------------------------------------------------
__global__ __launch_bounds__(256) void qproj_kernel(
    const float* __restrict__ input, const float* __restrict__ Wq) {
  const int warp = threadIdx.x >> 5;
  const int lane = threadIdx.x & 31;
  const int dtile = blockIdx.x * 16;
  const int ks = blockIdx.y;            // 0..1
  const int k0 = ks * 512;

#pragma unroll
  for (int dd = 0; dd < 2; ++dd) {
    const int d = dtile + warp * 2 + dd;
    float acc[32];
#pragma unroll
    for (int b = 0; b < 32; ++b) acc[b] = 0.f;

#pragma unroll
    for (int c = 0; c < 4; ++c) {
      const int k = k0 + c * 128 + lane * 4;
      const float4 w4 = *(const float4*)(Wq + (size_t)d * CC + k);
#pragma unroll
      for (int b = 0; b < 32; ++b) {
        const float4 in4 = *(const float4*)(input + b * CC + k);
        acc[b] += w4.x * in4.x + w4.y * in4.y + w4.z * in4.z + w4.w * in4.w;
      }
    }

    // log-depth exchange reduction: after this, acc[0] = total for b = lane
#pragma unroll
    for (int s = 16; s >= 1; s >>= 1) {
      const bool hi = (lane & s) != 0;
#pragma unroll
      for (int i = 0; i < 16; ++i) {
        if (i < s) {
          const float snd = hi ? acc[i] : acc[i + s];
          const float rcv = __shfl_xor_sync(0xffffffffu, snd, s);
          acc[i] = (hi ? acc[i + s] : acc[i]) + rcv;
        }
      }
    }
    g_qpart[ks][lane * DH + d] = acc[0];
  }
}

// ---------------------------------------------------------------------------
// Kernel B: fused scores + online-softmax weighted accumulation.
// grid (CHUNKS, BB), 256 threads. Thread j owns d in [4j, 4j+4) (float4).
// Per t: coalesced float4 load of the key fragment, block-reduced dot,
// raw score stored, online-softmax update of (m, l, a4).
// enc_h layout (D, T, B, H): keys[b,t,dir*H+h] = enc_h[((dir*T+t)*B+b)*H+h]
// ---------------------------------------------------------------------------
__global__ __launch_bounds__(256) void attn_main_kernel(
    const float* __restrict__ enc_h, const float* __restrict__ bq) {
  const int chunk = blockIdx.x;
  const int b = blockIdx.y;
  const int t0 = chunk * TC;
  const int j = threadIdx.x;           // 0..255
  const int warp = j >> 5;
  const int lane = j & 31;
  const int d = 4 * j;
  const int dir = d >> 9;              // 0 if d<512 else 1
  const int h = d & 511;

  // assemble q (partials + bias)
  const float4 p0 = *(const float4*)(&g_qpart[0][b * DH + d]);
  const float4 p1 = *(const float4*)(&g_qpart[1][b * DH + d]);
  const float4 bq4 = *(const float4*)(bq + d);
  float4 q;
  q.x = p0.x + p1.x + bq4.x;
  q.y = p0.y + p1.y + bq4.y;
  q.z = p0.z + p1.z + bq4.z;
  q.w = p0.w + p1.w + bq4.w;

  const float* base = enc_h + ((size_t)(dir * TT + t0) * BB + b) * HH + h;
  const size_t tstride = (size_t)BB * HH;  // 16384 floats per timestep

  const float scale = 0.04419417382415922f;  // 1/sqrt(512)

  float4 a = make_float4(0.f, 0.f, 0.f, 0.f);
  float m = -1e30f, l = 0.f;

  __shared__ float red[8][4];

#pragma unroll 1
  for (int it = 0; it < TC / 4; ++it) {
    const float* p = base + (size_t)(4 * it) * tstride;
    const float4 k0v = *(const float4*)(p);
    const float4 k1v = *(const float4*)(p + tstride);
    const float4 k2v = *(const float4*)(p + 2 * tstride);
    const float4 k3v = *(const float4*)(p + 3 * tstride);

    float s0 = q.x * k0v.x + q.y * k0v.y + q.z * k0v.z + q.w * k0v.w;
    float s1 = q.x * k1v.x + q.y * k1v.y + q.z * k1v.z + q.w * k1v.w;
    float s2 = q.x * k2v.x + q.y * k2v.y + q.z * k2v.z + q.w * k2v.w;
    float s3 = q.x * k3v.x + q.y * k3v.y + q.z * k3v.z + q.w * k3v.w;

#pragma unroll
    for (int off = 16; off >= 1; off >>= 1) {
      s0 += __shfl_xor_sync(0xffffffffu, s0, off);
      s1 += __shfl_xor_sync(0xffffffffu, s1, off);
      s2 += __shfl_xor_sync(0xffffffffu, s2, off);
      s3 += __shfl_xor_sync(0xffffffffu, s3, off);
    }
    if (lane == 0) {
      red[warp][0] = s0;
      red[warp][1] = s1;
      red[warp][2] = s2;
      red[warp][3] = s3;
    }
    __syncthreads();
    float t_s0 = 0.f, t_s1 = 0.f, t_s2 = 0.f, t_s3 = 0.f;
#pragma unroll
    for (int w = 0; w < 8; ++w) {
      t_s0 += red[w][0];
      t_s1 += red[w][1];
      t_s2 += red[w][2];
      t_s3 += red[w][3];
    }
    __syncthreads();
    t_s0 *= scale; t_s1 *= scale; t_s2 *= scale; t_s3 *= scale;

    if (j == 0) {
      float* sp = g_scores + b * TT + t0 + 4 * it;
      sp[0] = t_s0; sp[1] = t_s1; sp[2] = t_s2; sp[3] = t_s3;
    }

    // online softmax updates (identical m,l math on every thread)
#define ONLINE_STEP(SV, KV)                                          \
    {                                                                \
      const float sv = (SV);                                         \
      if (sv > m) {                                                  \
        const float r = __expf(m - sv);                              \
        a.x *= r; a.y *= r; a.z *= r; a.w *= r;                      \
        l *= r; m = sv;                                              \
      }                                                              \
      const float wgt = __expf(sv - m);                              \
      l += wgt;                                                      \
      a.x += wgt * (KV).x; a.y += wgt * (KV).y;                      \
      a.z += wgt * (KV).z; a.w += wgt * (KV).w;                      \
    }
    ONLINE_STEP(t_s0, k0v)
    ONLINE_STEP(t_s1, k1v)
    ONLINE_STEP(t_s2, k2v)
    ONLINE_STEP(t_s3, k3v)
#undef ONLINE_STEP
  }

  *(float4*)(g_pa + (size_t)(b * CHUNKS + chunk) * DH + d) = a;
  if (j == 0) {
    g_pm[b * CHUNKS + chunk] = m;
    g_pl[b * CHUNKS + chunk] = l;
  }
}

// ---------------------------------------------------------------------------
// Kernel C: combine per-chunk partials -> attn_values (first 32768 floats of out)
// grid (BB), 256 threads, thread j owns d in [4j,4j+4)
// ---------------------------------------------------------------------------
__global__ __launch_bounds__(256) void combine_kernel(float* __restrict__ out) {
  const int b = blockIdx.x;
  const int j = threadIdx.x;

  __shared__ float sm[CHUNKS], sl[CHUNKS];
  if (j < CHUNKS) {
    sm[j] = g_pm[b * CHUNKS + j];
    sl[j] = g_pl[b * CHUNKS + j];
  }
  __syncthreads();

  float M = -1e30f;
#pragma unroll
  for (int c = 0; c < CHUNKS; ++c) M = fmaxf(M, sm[c]);
  float L = 0.f;
#pragma unroll
  for (int c = 0; c < CHUNKS; ++c) L += sl[c] * __expf(sm[c] - M);
  const float invL = 1.f / L;

  float4 v = make_float4(0.f, 0.f, 0.f, 0.f);
#pragma unroll
  for (int c = 0; c < CHUNKS; ++c) {
    const float wc = __expf(sm[c] - M);
    const float4 pa =
        *(const float4*)(g_pa + (size_t)(b * CHUNKS + c) * DH + 4 * j);
    v.x += wc * pa.x; v.y += wc * pa.y; v.z += wc * pa.z; v.w += wc * pa.w;
  }
  v.x *= invL; v.y *= invL; v.z *= invL; v.w *= invL;
  *(float4*)(out + b * DH + 4 * j) = v;

  if (j == 0) {
    g_M[b] = M;
    g_invL[b] = invL;
  }
}

// ---------------------------------------------------------------------------
// Kernel D: normalized scores -> out[32768 .. 32768+65536)
// ---------------------------------------------------------------------------
__global__ __launch_bounds__(256) void scores_kernel(float* __restrict__ out) {
  const int idx = blockIdx.x * 256 + threadIdx.x;  // 0..65535
  const int b = idx >> 11;                         // /2048
  out[BB * DH + idx] = __expf(g_scores[idx] - g_M[b]) * g_invL[b];
}

// ---------------------------------------------------------------------------
extern "C" void kernel_launch(void* const* d_in, const int* in_sizes, int n_in,
                              void* d_out, int out_size) {
  const float* input = (const float*)d_in[0];   // (32, 1024)
  const float* enc_h = (const float*)d_in[1];   // (2, 2048, 32, 512)
  // d_in[2] decoder_state: unused
  const float* Wq = (const float*)d_in[3];      // (1024, 1024)
  const float* bq = (const float*)d_in[4];      // (1024,)
  // d_in[5] t: unused
  float* out = (float*)d_out;  // [attn_values (32*1024)] ++ [attn_scores (32*2048)]

  qproj_kernel<<<dim3(64, 2), 256>>>(input, Wq);
  attn_main_kernel<<<dim3(CHUNKS, BB), 256>>>(enc_h, bq);
  combine_kernel<<<BB, 256>>>(out);
  scores_kernel<<<(BB * TT) / 256, 256>>>(out);
}

// round 2
// speedup vs baseline: 1.0119x; 1.0119x over previous
#include <cuda_runtime.h>
#include <cuda_bf16.h>

// Problem constants (fixed by setup_inputs)
#define BB 32      // batch
#define TT 2048    // timesteps
#define HH 512     // hidden per direction
#define DH 1024    // D*H
#define CC 1024    // input feature size
#define NWARP 128  // partial warps per batch
#define WT (TT / NWARP)  // 16 timesteps per warp

// ---------------- scratch (no runtime allocation allowed) ----------------
__device__ float g_qpart[2][BB * DH];              // K-split partial query proj
__device__ float g_scores[BB * TT];                // raw (pre-softmax) scores
__device__ float g_pm[BB * NWARP];                 // per-warp running max
__device__ float g_pl[BB * NWARP];                 // per-warp running sum
__device__ float g_pa[(size_t)BB * NWARP * DH];    // per-warp weighted accum (16 MB)
__device__ float g_M[BB];                          // global max per batch
__device__ float g_invL[BB];                       // 1/denominator per batch

// ---------------------------------------------------------------------------
// Kernel A: query projection partials.
//   q[b,d] = sum_c input[b,c] * Wq[d,c]   (bq added later in kernel B)
// ---------------------------------------------------------------------------
__global__ __launch_bounds__(256) void qproj_kernel(
    const float* __restrict__ input, const float* __restrict__ Wq) {
  const int warp = threadIdx.x >> 5;
  const int lane = threadIdx.x & 31;
  const int dtile = blockIdx.x * 16;
  const int ks = blockIdx.y;            // 0..1
  const int k0 = ks * 512;

#pragma unroll
  for (int dd = 0; dd < 2; ++dd) {
    const int d = dtile + warp * 2 + dd;
    float acc[32];
#pragma unroll
    for (int b = 0; b < 32; ++b) acc[b] = 0.f;

#pragma unroll
    for (int c = 0; c < 4; ++c) {
      const int k = k0 + c * 128 + lane * 4;
      const float4 w4 = *(const float4*)(Wq + (size_t)d * CC + k);
#pragma unroll
      for (int b = 0; b < 32; ++b) {
        const float4 in4 = *(const float4*)(input + b * CC + k);
        acc[b] += w4.x * in4.x + w4.y * in4.y + w4.z * in4.z + w4.w * in4.w;
      }
    }

    // log-depth exchange reduction: leaves total for b = lane in acc[0]
#pragma unroll
    for (int s = 16; s >= 1; s >>= 1) {
      const bool hi = (lane & s) != 0;
#pragma unroll
      for (int i = 0; i < 16; ++i) {
        if (i < s) {
          const float snd = hi ? acc[i] : acc[i + s];
          const float rcv = __shfl_xor_sync(0xffffffffu, snd, s);
          acc[i] = (hi ? acc[i + s] : acc[i]) + rcv;
        }
      }
    }
    g_qpart[ks][lane * DH + d] = acc[0];
  }
}

// ---------------------------------------------------------------------------
// Kernel B: warp-autonomous fused scores + online-softmax accumulation.
// grid (NWARP/4, BB), 128 threads (4 warps). Each warp owns WT=16 whole
// timesteps: per t it loads the full 1024-d key row (8 x float4 per lane),
// reduces the dot with 5 shfl (NO block barriers), and updates its private
// a[1024] (8 x float4 per lane) with online softmax. Per-warp partials out.
// enc_h layout (D, T, B, H): keys[b,t,dir*H+h] = enc_h[((dir*T+t)*B+b)*H+h]
// ---------------------------------------------------------------------------
__global__ __launch_bounds__(128, 3) void attn_main_kernel(
    const float* __restrict__ enc_h, const float* __restrict__ bq) {
  const int b = blockIdx.y;
  const int warp = threadIdx.x >> 5;
  const int lane = threadIdx.x & 31;
  const int widx = blockIdx.x * 4 + warp;   // 0..NWARP-1 within this batch
  const int t0 = widx * WT;

  const float scale = 0.04419417382415922f;  // 1/sqrt(512)

  // q for this lane: q[p] covers d = p*128 + lane*4
  float4 q[8];
#pragma unroll
  for (int p = 0; p < 8; ++p) {
    const int d = p * 128 + lane * 4;
    const float4 p0 = *(const float4*)(&g_qpart[0][b * DH + d]);
    const float4 p1 = *(const float4*)(&g_qpart[1][b * DH + d]);
    const float4 bb = *(const float4*)(bq + d);
    q[p].x = p0.x + p1.x + bb.x;
    q[p].y = p0.y + p1.y + bb.y;
    q[p].z = p0.z + p1.z + bb.z;
    q[p].w = p0.w + p1.w + bb.w;
  }

  float4 a[8];
#pragma unroll
  for (int p = 0; p < 8; ++p) a[p] = make_float4(0.f, 0.f, 0.f, 0.f);
  float m = -1e30f, l = 0.f;

  const size_t tstride = (size_t)BB * HH;          // floats per timestep
  const size_t dirstride = (size_t)TT * BB * HH;   // floats per direction
  const float* base0 = enc_h + ((size_t)t0 * BB + b) * HH + lane * 4;
  const float* base1 = base0 + dirstride;

#pragma unroll 2
  for (int i = 0; i < WT; ++i) {
    const float* r0 = base0 + (size_t)i * tstride;
    const float* r1 = base1 + (size_t)i * tstride;
    float4 k[8];
#pragma unroll
    for (int p = 0; p < 4; ++p) k[p] = *(const float4*)(r0 + p * 128);
#pragma unroll
    for (int p = 0; p < 4; ++p) k[p + 4] = *(const float4*)(r1 + p * 128);

    float s = 0.f;
#pragma unroll
    for (int p = 0; p < 8; ++p)
      s += q[p].x * k[p].x + q[p].y * k[p].y + q[p].z * k[p].z + q[p].w * k[p].w;
#pragma unroll
    for (int off = 16; off >= 1; off >>= 1)
      s += __shfl_xor_sync(0xffffffffu, s, off);
    s *= scale;

    if (lane == 0) g_scores[b * TT + t0 + i] = s;

    if (s > m) {   // warp-uniform branch (s identical on all lanes)
      const float r = __expf(m - s);
#pragma unroll
      for (int p = 0; p < 8; ++p) {
        a[p].x *= r; a[p].y *= r; a[p].z *= r; a[p].w *= r;
      }
      l *= r;
      m = s;
    }
    const float w = __expf(s - m);
    l += w;
#pragma unroll
    for (int p = 0; p < 8; ++p) {
      a[p].x += w * k[p].x;
      a[p].y += w * k[p].y;
      a[p].z += w * k[p].z;
      a[p].w += w * k[p].w;
    }
  }

  float* pa = g_pa + (size_t)(b * NWARP + widx) * DH + lane * 4;
#pragma unroll
  for (int p = 0; p < 8; ++p) *(float4*)(pa + p * 128) = a[p];
  if (lane == 0) {
    g_pm[b * NWARP + widx] = m;
    g_pl[b * NWARP + widx] = l;
  }
}

// ---------------------------------------------------------------------------
// Kernel C: combine per-warp partials -> attn_values (first 32768 floats).
// grid (BB, 4): block handles 256 d's of one batch. Scalar coalesced loads.
// ---------------------------------------------------------------------------
__global__ __launch_bounds__(256) void combine_kernel(float* __restrict__ out) {
  const int b = blockIdx.x;
  const int ds = blockIdx.y;
  const int j = threadIdx.x;

  __shared__ float sm[NWARP], sl[NWARP], sw[NWARP];
  if (j < NWARP) {
    sm[j] = g_pm[b * NWARP + j];
    sl[j] = g_pl[b * NWARP + j];
  }
  __syncthreads();

  float M = -1e30f;
#pragma unroll
  for (int w = 0; w < NWARP; ++w) M = fmaxf(M, sm[w]);
  if (j < NWARP) sw[j] = __expf(sm[j] - M);
  __syncthreads();

  float L = 0.f;
#pragma unroll
  for (int w = 0; w < NWARP; ++w) L += sl[w] * sw[w];
  const float invL = 1.f / L;

  const int d = ds * 256 + j;
  const float* pa = g_pa + (size_t)b * NWARP * DH + d;
  float v = 0.f;
#pragma unroll 8
  for (int w = 0; w < NWARP; ++w) v += sw[w] * pa[(size_t)w * DH];
  out[b * DH + d] = v * invL;

  if (ds == 0 && j == 0) {
    g_M[b] = M;
    g_invL[b] = invL;
  }
}

// ---------------------------------------------------------------------------
// Kernel D: normalized scores -> out[32768 .. 32768+65536), float4 per thread
// ---------------------------------------------------------------------------
__global__ __launch_bounds__(256) void scores_kernel(float* __restrict__ out) {
  const int g = blockIdx.x * 256 + threadIdx.x;  // 0..16383
  const int idx = g * 4;
  const int b = idx >> 11;                       // /2048 (4-aligned, same b)
  const float M = g_M[b];
  const float invL = g_invL[b];
  const float4 s = *(const float4*)(g_scores + idx);
  float4 o;
  o.x = __expf(s.x - M) * invL;
  o.y = __expf(s.y - M) * invL;
  o.z = __expf(s.z - M) * invL;
  o.w = __expf(s.w - M) * invL;
  *(float4*)(out + BB * DH + idx) = o;
}

// ---------------------------------------------------------------------------
extern "C" void kernel_launch(void* const* d_in, const int* in_sizes, int n_in,
                              void* d_out, int out_size) {
  const float* input = (const float*)d_in[0];   // (32, 1024)
  const float* enc_h = (const float*)d_in[1];   // (2, 2048, 32, 512)
  // d_in[2] decoder_state: unused
  const float* Wq = (const float*)d_in[3];      // (1024, 1024)
  const float* bq = (const float*)d_in[4];      // (1024,)
  // d_in[5] t: unused
  float* out = (float*)d_out;  // [attn_values (32*1024)] ++ [attn_scores (32*2048)]

  qproj_kernel<<<dim3(64, 2), 256>>>(input, Wq);
  attn_main_kernel<<<dim3(NWARP / 4, BB), 128>>>(enc_h, bq);
  combine_kernel<<<dim3(BB, 4), 256>>>(out);
  scores_kernel<<<(BB * TT) / (256 * 4), 256>>>(out);
}

// round 3
// speedup vs baseline: 1.7331x; 1.7127x over previous
#include <cuda_runtime.h>
#include <cuda_bf16.h>

// Problem constants (fixed by setup_inputs)
#define BB 32      // batch
#define TT 2048    // timesteps
#define HH 512     // hidden per direction
#define DH 1024    // D*H
#define CC 1024    // input feature size
#define NWARP 128  // partial warps per batch
#define WT (TT / NWARP)  // 16 timesteps per warp

// ---------------- scratch (no runtime allocation allowed) ----------------
__device__ float g_q[BB * DH];                     // projected query (+bias)
__device__ float g_scores[BB * TT];                // raw (pre-softmax) scores
__device__ float g_pm[BB * NWARP];                 // per-warp running max
__device__ float g_pl[BB * NWARP];                 // per-warp running sum
__device__ float g_pa[(size_t)BB * NWARP * DH];    // per-warp weighted accum (16 MB)
__device__ float g_M[BB];                          // global max per batch
__device__ float g_invL[BB];                       // 1/denominator per batch

// ---------------------------------------------------------------------------
// Kernel A: query projection.  q[b,d] = sum_c input[b,c]*Wq[d,c] + bq[d]
// grid 128 blocks x 256 thr: warp handles one d over full K=1024.
// Warp-cooperative over k, 32 batch accumulators, log-depth multi-value
// shuffle exchange leaves the total for b = lane in acc[0].
// ---------------------------------------------------------------------------
__global__ __launch_bounds__(256) void qproj_kernel(
    const float* __restrict__ input, const float* __restrict__ Wq,
    const float* __restrict__ bq) {
  const int warp = threadIdx.x >> 5;
  const int lane = threadIdx.x & 31;
  const int d = blockIdx.x * 8 + warp;

  float acc[32];
#pragma unroll
  for (int b = 0; b < 32; ++b) acc[b] = 0.f;

#pragma unroll
  for (int c = 0; c < 8; ++c) {
    const int k = c * 128 + lane * 4;
    const float4 w4 = *(const float4*)(Wq + (size_t)d * CC + k);
#pragma unroll
    for (int b = 0; b < 32; ++b) {
      const float4 in4 = *(const float4*)(input + b * CC + k);
      acc[b] += w4.x * in4.x + w4.y * in4.y + w4.z * in4.z + w4.w * in4.w;
    }
  }

  // log-depth exchange reduction: leaves total for b = lane in acc[0]
#pragma unroll
  for (int s = 16; s >= 1; s >>= 1) {
    const bool hi = (lane & s) != 0;
#pragma unroll
    for (int i = 0; i < 16; ++i) {
      if (i < s) {
        const float snd = hi ? acc[i] : acc[i + s];
        const float rcv = __shfl_xor_sync(0xffffffffu, snd, s);
        acc[i] = (hi ? acc[i + s] : acc[i]) + rcv;
      }
    }
  }
  g_q[lane * DH + d] = acc[0] + bq[d];
}

// ---------------------------------------------------------------------------
// Kernel B: warp-autonomous fused scores + online-softmax accumulation,
// with q in SMEM and explicit double-buffered key prefetch.
// grid (NWARP/4, BB), 128 threads (4 warps). Warp owns WT=16 timesteps.
// enc_h layout (D, T, B, H): keys[b,t,dir*H+h] = enc_h[((dir*T+t)*B+b)*H+h]
// ---------------------------------------------------------------------------
__global__ __launch_bounds__(128, 3) void attn_main_kernel(
    const float* __restrict__ enc_h) {
  const int b = blockIdx.y;
  const int warp = threadIdx.x >> 5;
  const int lane = threadIdx.x & 31;
  const int widx = blockIdx.x * 4 + warp;   // 0..NWARP-1 within this batch
  const int t0 = widx * WT;

  const float scale = 0.04419417382415922f;  // 1/sqrt(512)

  // q for this batch, staged in smem as float4[256]
  __shared__ float4 sq[256];
  {
    const float4* gq4 = (const float4*)(g_q + b * DH);
    sq[threadIdx.x] = gq4[threadIdx.x];
    sq[threadIdx.x + 128] = gq4[threadIdx.x + 128];
  }
  __syncthreads();

  float4 a[8];
#pragma unroll
  for (int p = 0; p < 8; ++p) a[p] = make_float4(0.f, 0.f, 0.f, 0.f);
  float m = -1e30f, l = 0.f;

  const size_t tstride = (size_t)BB * HH;          // floats per timestep
  const size_t dirstride = (size_t)TT * BB * HH;   // floats per direction
  const float* base0 = enc_h + ((size_t)t0 * BB + b) * HH + lane * 4;
  const float* base1 = base0 + dirstride;

  float4 ka[8], kb[8];

#define LOADK(BUF, I)                                                      \
  {                                                                        \
    const float* r0_ = base0 + (size_t)(I)*tstride;                        \
    const float* r1_ = base1 + (size_t)(I)*tstride;                        \
    BUF[0] = *(const float4*)(r0_);                                        \
    BUF[1] = *(const float4*)(r0_ + 128);                                  \
    BUF[2] = *(const float4*)(r0_ + 256);                                  \
    BUF[3] = *(const float4*)(r0_ + 384);                                  \
    BUF[4] = *(const float4*)(r1_);                                        \
    BUF[5] = *(const float4*)(r1_ + 128);                                  \
    BUF[6] = *(const float4*)(r1_ + 256);                                  \
    BUF[7] = *(const float4*)(r1_ + 384);                                  \
  }

#define STEPK(BUF, I)                                                      \
  {                                                                        \
    float s = 0.f;                                                         \
    _Pragma("unroll") for (int p = 0; p < 8; ++p) {                        \
      const float4 qv = sq[p * 32 + lane];                                 \
      s += qv.x * BUF[p].x + qv.y * BUF[p].y + qv.z * BUF[p].z +           \
           qv.w * BUF[p].w;                                                \
    }                                                                      \
    _Pragma("unroll") for (int off = 16; off >= 1; off >>= 1)              \
        s += __shfl_xor_sync(0xffffffffu, s, off);                         \
    s *= scale;                                                            \
    if (lane == 0) g_scores[b * TT + t0 + (I)] = s;                        \
    if (s > m) { /* warp-uniform */                                        \
      const float r_ = __expf(m - s);                                      \
      _Pragma("unroll") for (int p = 0; p < 8; ++p) {                      \
        a[p].x *= r_; a[p].y *= r_; a[p].z *= r_; a[p].w *= r_;            \
      }                                                                    \
      l *= r_;                                                             \
      m = s;                                                               \
    }                                                                      \
    const float w_ = __expf(s - m);                                        \
    l += w_;                                                               \
    _Pragma("unroll") for (int p = 0; p < 8; ++p) {                        \
      a[p].x += w_ * BUF[p].x;                                             \
      a[p].y += w_ * BUF[p].y;                                             \
      a[p].z += w_ * BUF[p].z;                                             \
      a[p].w += w_ * BUF[p].w;                                             \
    }                                                                      \
  }

  LOADK(ka, 0)
#pragma unroll
  for (int i = 0; i < WT; i += 2) {
    LOADK(kb, i + 1)      // prefetch t+1 before t's math
    STEPK(ka, i)
    if (i + 2 < WT) LOADK(ka, i + 2)  // prefetch t+2 before t+1's math
    STEPK(kb, i + 1)
  }
#undef LOADK
#undef STEPK

  float* pa = g_pa + (size_t)(b * NWARP + widx) * DH + lane * 4;
#pragma unroll
  for (int p = 0; p < 8; ++p) *(float4*)(pa + p * 128) = a[p];
  if (lane == 0) {
    g_pm[b * NWARP + widx] = m;
    g_pl[b * NWARP + widx] = l;
  }
}

// ---------------------------------------------------------------------------
// Kernel C: combine per-warp partials -> attn_values (first 32768 floats).
// grid (BB, 8), 128 threads: block handles 128 d's of one batch.
// 4 split accumulators + unroll 16 for MLP.
// ---------------------------------------------------------------------------
__global__ __launch_bounds__(128) void combine_kernel(float* __restrict__ out) {
  const int b = blockIdx.x;
  const int ds = blockIdx.y;
  const int j = threadIdx.x;

  __shared__ float sm[NWARP], sl[NWARP], sw[NWARP];
  sm[j] = g_pm[b * NWARP + j];
  sl[j] = g_pl[b * NWARP + j];
  __syncthreads();

  float M = -1e30f;
#pragma unroll
  for (int w = 0; w < NWARP; ++w) M = fmaxf(M, sm[w]);
  sw[j] = __expf(sm[j] - M);
  __syncthreads();

  float L = 0.f;
#pragma unroll
  for (int w = 0; w < NWARP; ++w) L += sl[w] * sw[w];
  const float invL = 1.f / L;

  const int d = ds * 128 + j;
  const float* pa = g_pa + (size_t)b * NWARP * DH + d;
  float v0 = 0.f, v1 = 0.f, v2 = 0.f, v3 = 0.f;
#pragma unroll 4
  for (int w = 0; w < NWARP; w += 4) {
    v0 += sw[w + 0] * pa[(size_t)(w + 0) * DH];
    v1 += sw[w + 1] * pa[(size_t)(w + 1) * DH];
    v2 += sw[w + 2] * pa[(size_t)(w + 2) * DH];
    v3 += sw[w + 3] * pa[(size_t)(w + 3) * DH];
  }
  out[b * DH + d] = (v0 + v1 + v2 + v3) * invL;

  if (ds == 0 && j == 0) {
    g_M[b] = M;
    g_invL[b] = invL;
  }
}

// ---------------------------------------------------------------------------
// Kernel D: normalized scores -> out[32768 .. 32768+65536), float4 per thread
// ---------------------------------------------------------------------------
__global__ __launch_bounds__(256) void scores_kernel(float* __restrict__ out) {
  const int g = blockIdx.x * 256 + threadIdx.x;  // 0..16383
  const int idx = g * 4;
  const int b = idx >> 11;                       // /2048 (4-aligned, same b)
  const float M = g_M[b];
  const float invL = g_invL[b];
  const float4 s = *(const float4*)(g_scores + idx);
  float4 o;
  o.x = __expf(s.x - M) * invL;
  o.y = __expf(s.y - M) * invL;
  o.z = __expf(s.z - M) * invL;
  o.w = __expf(s.w - M) * invL;
  *(float4*)(out + BB * DH + idx) = o;
}

// ---------------------------------------------------------------------------
extern "C" void kernel_launch(void* const* d_in, const int* in_sizes, int n_in,
                              void* d_out, int out_size) {
  const float* input = (const float*)d_in[0];   // (32, 1024)
  const float* enc_h = (const float*)d_in[1];   // (2, 2048, 32, 512)
  // d_in[2] decoder_state: unused
  const float* Wq = (const float*)d_in[3];      // (1024, 1024)
  const float* bq = (const float*)d_in[4];      // (1024,)
  // d_in[5] t: unused
  float* out = (float*)d_out;  // [attn_values (32*1024)] ++ [attn_scores (32*2048)]

  qproj_kernel<<<128, 256>>>(input, Wq, bq);
  attn_main_kernel<<<dim3(NWARP / 4, BB), 128>>>(enc_h);
  combine_kernel<<<dim3(BB, 8), 128>>>(out);
  scores_kernel<<<(BB * TT) / (256 * 4), 256>>>(out);
}

// round 4
// speedup vs baseline: 1.9095x; 1.1018x over previous
#include <cuda_runtime.h>
#include <cuda_bf16.h>

// Problem constants (fixed by setup_inputs)
#define BB 32      // batch
#define TT 2048    // timesteps
#define HH 512     // hidden per direction
#define DH 1024    // D*H
#define CC 1024    // input feature size
#define NWARP 128  // partial warps per batch
#define WT (TT / NWARP)  // 16 timesteps per warp
#define SSTAGES 4  // smem ring stages per warp (1 timestep = 4KB each)
#define PRE 3      // stages kept in flight

// ---------------- scratch (no runtime allocation allowed) ----------------
__device__ float g_q[BB * DH];                     // projected query (+bias)
__device__ float g_scores[BB * TT];                // raw (pre-softmax) scores
__device__ float g_pm[BB * NWARP];                 // per-warp running max
__device__ float g_pl[BB * NWARP];                 // per-warp running sum
__device__ float g_pa[(size_t)BB * NWARP * DH];    // per-warp weighted accum (16 MB)

// ---------------------------------------------------------------------------
// Kernel A: query projection.  q[b,d] = sum_c input[b,c]*Wq[d,c] + bq[d]
// ---------------------------------------------------------------------------
__global__ __launch_bounds__(256) void qproj_kernel(
    const float* __restrict__ input, const float* __restrict__ Wq,
    const float* __restrict__ bq) {
  const int warp = threadIdx.x >> 5;
  const int lane = threadIdx.x & 31;
  const int d = blockIdx.x * 8 + warp;

  float acc[32];
#pragma unroll
  for (int b = 0; b < 32; ++b) acc[b] = 0.f;

#pragma unroll
  for (int c = 0; c < 8; ++c) {
    const int k = c * 128 + lane * 4;
    const float4 w4 = *(const float4*)(Wq + (size_t)d * CC + k);
#pragma unroll
    for (int b = 0; b < 32; ++b) {
      const float4 in4 = *(const float4*)(input + b * CC + k);
      acc[b] += w4.x * in4.x + w4.y * in4.y + w4.z * in4.z + w4.w * in4.w;
    }
  }

  // log-depth exchange reduction: leaves total for b = lane in acc[0]
#pragma unroll
  for (int s = 16; s >= 1; s >>= 1) {
    const bool hi = (lane & s) != 0;
#pragma unroll
    for (int i = 0; i < 16; ++i) {
      if (i < s) {
        const float snd = hi ? acc[i] : acc[i + s];
        const float rcv = __shfl_xor_sync(0xffffffffu, snd, s);
        acc[i] = (hi ? acc[i + s] : acc[i]) + rcv;
      }
    }
  }
  g_q[lane * DH + d] = acc[0] + bq[d];
}

// ---------------------------------------------------------------------------
// Kernel B: warp-autonomous fused scores + online softmax, cp.async pipeline.
// grid (NWARP/4, BB), 128 threads (4 warps). Warp owns WT=16 timesteps;
// keys are staged global->smem with LDGSTS (no register cost), PRE=3 stages
// (12 KB/warp) permanently in flight. Each lane reads back exactly the bytes
// it copied, so only cp.async.wait_group ordering is needed (no barriers).
// enc_h layout (D, T, B, H): keys[b,t,dir*H+h] = enc_h[((dir*T+t)*B+b)*H+h]
// ---------------------------------------------------------------------------
__global__ __launch_bounds__(128, 3) void attn_main_kernel(
    const float* __restrict__ enc_h) {
  const int b = blockIdx.y;
  const int warp = threadIdx.x >> 5;
  const int lane = threadIdx.x & 31;
  const int widx = blockIdx.x * 4 + warp;   // 0..NWARP-1 within this batch
  const int t0 = widx * WT;

  const float scale = 0.04419417382415922f;  // 1/sqrt(512)

  extern __shared__ float4 ring[];           // [4 warps][SSTAGES][256]
  float4* ringw = ring + warp * (SSTAGES * 256);

  // q for this lane in registers: q[p] covers d = p*128 + lane*4
  float4 q[8];
#pragma unroll
  for (int p = 0; p < 8; ++p)
    q[p] = *(const float4*)(&g_q[b * DH + p * 128 + lane * 4]);

  float4 a[8];
#pragma unroll
  for (int p = 0; p < 8; ++p) a[p] = make_float4(0.f, 0.f, 0.f, 0.f);
  float m = -1e30f, l = 0.f;

  const size_t tstride = (size_t)BB * HH;          // floats per timestep
  const size_t dirstride = (size_t)TT * BB * HH;   // floats per direction
  const float* base0 = enc_h + ((size_t)t0 * BB + b) * HH + lane * 4;
  const float* base1 = base0 + dirstride;

#define LOAD_STAGE(T)                                                        \
  {                                                                          \
    const int slot_ = (T) & (SSTAGES - 1);                                   \
    const float* r0_ = base0 + (size_t)(T)*tstride;                          \
    const float* r1_ = base1 + (size_t)(T)*tstride;                          \
    float4* d_ = ringw + slot_ * 256 + lane;                                 \
    _Pragma("unroll") for (int p = 0; p < 4; ++p) {                          \
      unsigned sa_ = (unsigned)__cvta_generic_to_shared(d_ + p * 32);        \
      asm volatile("cp.async.cg.shared.global [%0], [%1], 16;" ::"r"(sa_),   \
                   "l"(r0_ + p * 128));                                      \
    }                                                                        \
    _Pragma("unroll") for (int p = 0; p < 4; ++p) {                          \
      unsigned sa_ = (unsigned)__cvta_generic_to_shared(d_ + 128 + p * 32);  \
      asm volatile("cp.async.cg.shared.global [%0], [%1], 16;" ::"r"(sa_),   \
                   "l"(r1_ + p * 128));                                      \
    }                                                                        \
  }

  // prologue: stages 0..PRE-1 in flight (one commit group per stage)
#pragma unroll
  for (int i = 0; i < PRE; ++i) {
    LOAD_STAGE(i)
    asm volatile("cp.async.commit_group;");
  }

#pragma unroll
  for (int i = 0; i < WT; ++i) {
    if (i + PRE < WT) LOAD_STAGE(i + PRE)
    asm volatile("cp.async.commit_group;");  // empty group ok in tail
    asm volatile("cp.async.wait_group %0;" ::"n"(PRE));  // stage i ready

    const float4* kp = ringw + (i & (SSTAGES - 1)) * 256 + lane;
    float4 k[8];
#pragma unroll
    for (int p = 0; p < 8; ++p) k[p] = kp[p * 32];

    float s = 0.f;
#pragma unroll
    for (int p = 0; p < 8; ++p)
      s += q[p].x * k[p].x + q[p].y * k[p].y + q[p].z * k[p].z +
           q[p].w * k[p].w;
#pragma unroll
    for (int off = 16; off >= 1; off >>= 1)
      s += __shfl_xor_sync(0xffffffffu, s, off);
    s *= scale;

    if (lane == 0) g_scores[b * TT + t0 + i] = s;

    if (s > m) {  // warp-uniform branch (s identical on all lanes)
      const float r = __expf(m - s);
#pragma unroll
      for (int p = 0; p < 8; ++p) {
        a[p].x *= r; a[p].y *= r; a[p].z *= r; a[p].w *= r;
      }
      l *= r;
      m = s;
    }
    const float w = __expf(s - m);
    l += w;
#pragma unroll
    for (int p = 0; p < 8; ++p) {
      a[p].x += w * k[p].x;
      a[p].y += w * k[p].y;
      a[p].z += w * k[p].z;
      a[p].w += w * k[p].w;
    }
  }
#undef LOAD_STAGE

  float* pa = g_pa + (size_t)(b * NWARP + widx) * DH + lane * 4;
#pragma unroll
  for (int p = 0; p < 8; ++p) *(float4*)(pa + p * 128) = a[p];
  if (lane == 0) {
    g_pm[b * NWARP + widx] = m;
    g_pl[b * NWARP + widx] = l;
  }
}

// ---------------------------------------------------------------------------
// Kernel C: combine per-warp partials -> attn_values, AND normalized scores.
// grid (BB, 8), 128 threads: block handles 128 d's + 256 score elements.
// ---------------------------------------------------------------------------
__global__ __launch_bounds__(128) void combine_kernel(float* __restrict__ out) {
  const int b = blockIdx.x;
  const int ds = blockIdx.y;
  const int j = threadIdx.x;

  __shared__ float sm[NWARP], sl[NWARP], sw[NWARP];
  sm[j] = g_pm[b * NWARP + j];
  sl[j] = g_pl[b * NWARP + j];
  __syncthreads();

  float M = -1e30f;
#pragma unroll
  for (int w = 0; w < NWARP; ++w) M = fmaxf(M, sm[w]);
  sw[j] = __expf(sm[j] - M);
  __syncthreads();

  float L = 0.f;
#pragma unroll
  for (int w = 0; w < NWARP; ++w) L += sl[w] * sw[w];
  const float invL = 1.f / L;

  const int d = ds * 128 + j;
  const float* pa = g_pa + (size_t)b * NWARP * DH + d;
  float v0 = 0.f, v1 = 0.f, v2 = 0.f, v3 = 0.f;
#pragma unroll 4
  for (int w = 0; w < NWARP; w += 4) {
    v0 += sw[w + 0] * pa[(size_t)(w + 0) * DH];
    v1 += sw[w + 1] * pa[(size_t)(w + 1) * DH];
    v2 += sw[w + 2] * pa[(size_t)(w + 2) * DH];
    v3 += sw[w + 3] * pa[(size_t)(w + 3) * DH];
  }
  out[b * DH + d] = (v0 + v1 + v2 + v3) * invL;

  // fused scores normalization: this block covers t in [ds*256, ds*256+256)
  const int tb = ds * 256 + j * 2;
  const float2 s2 = *(const float2*)(g_scores + b * TT + tb);
  float2 o2;
  o2.x = __expf(s2.x - M) * invL;
  o2.y = __expf(s2.y - M) * invL;
  *(float2*)(out + BB * DH + b * TT + tb) = o2;
}

// ---------------------------------------------------------------------------
extern "C" void kernel_launch(void* const* d_in, const int* in_sizes, int n_in,
                              void* d_out, int out_size) {
  const float* input = (const float*)d_in[0];   // (32, 1024)
  const float* enc_h = (const float*)d_in[1];   // (2, 2048, 32, 512)
  // d_in[2] decoder_state: unused
  const float* Wq = (const float*)d_in[3];      // (1024, 1024)
  const float* bq = (const float*)d_in[4];      // (1024,)
  // d_in[5] t: unused
  float* out = (float*)d_out;  // [attn_values (32*1024)] ++ [attn_scores (32*2048)]

  const int smem_bytes = 4 * SSTAGES * 256 * sizeof(float4);  // 64 KB
  cudaFuncSetAttribute(attn_main_kernel,
                       cudaFuncAttributeMaxDynamicSharedMemorySize, smem_bytes);

  qproj_kernel<<<128, 256>>>(input, Wq, bq);
  attn_main_kernel<<<dim3(NWARP / 4, BB), 128, smem_bytes>>>(enc_h);
  combine_kernel<<<dim3(BB, 8), 128>>>(out);
}

// round 5
// speedup vs baseline: 2.6366x; 1.3808x over previous
#include <cuda_runtime.h>
#include <cuda_bf16.h>

// Problem constants (fixed by setup_inputs)
#define BB 32      // batch
#define TT 2048    // timesteps
#define HH 512     // hidden per direction
#define DH 1024    // D*H
#define CC 1024    // input feature size
#define NWARP 128  // fused-pass warps per batch
#define WT (TT / NWARP)  // 16 timesteps per warp
#define NPART 32   // merged partials per batch (one per block)
#define SSTAGES 4  // smem ring stages per warp (1 timestep = 4KB each)
#define PRE 3      // stages kept in flight
#define KSPLIT 4   // qproj K-split

// ---------------- scratch (no runtime allocation allowed) ----------------
__device__ float g_qpart[KSPLIT][BB * DH];         // split-K query partials
__device__ float g_scores[BB * TT];                // raw (pre-softmax) scores
__device__ float g_pm[BB * NPART];                 // per-block running max
__device__ float g_pl[BB * NPART];                 // per-block running sum
__device__ float g_pa[(size_t)BB * NPART * DH];    // per-block weighted accum (4 MB)

// ---------------------------------------------------------------------------
// Kernel A: query projection partials (split-K x4).
//   qpart[ks][b,d] = sum_{k in ks-slice} input[b,k]*Wq[d,k]
// grid (128, KSPLIT) x 256 thr: warp handles one d over 256 k's.
// 32 batch accumulators; log-depth multi-value shuffle exchange leaves the
// total for b = lane in acc[0].
// ---------------------------------------------------------------------------
__global__ __launch_bounds__(256) void qproj_kernel(
    const float* __restrict__ input, const float* __restrict__ Wq) {
  const int warp = threadIdx.x >> 5;
  const int lane = threadIdx.x & 31;
  const int d = blockIdx.x * 8 + warp;
  const int k0 = blockIdx.y * (CC / KSPLIT);

  float acc[32];
#pragma unroll
  for (int b = 0; b < 32; ++b) acc[b] = 0.f;

#pragma unroll
  for (int c = 0; c < CC / KSPLIT / 128; ++c) {   // 2 iterations
    const int k = k0 + c * 128 + lane * 4;
    const float4 w4 = *(const float4*)(Wq + (size_t)d * CC + k);
#pragma unroll
    for (int b = 0; b < 32; ++b) {
      const float4 in4 = *(const float4*)(input + b * CC + k);
      acc[b] += w4.x * in4.x + w4.y * in4.y + w4.z * in4.z + w4.w * in4.w;
    }
  }

  // log-depth exchange reduction: leaves total for b = lane in acc[0]
#pragma unroll
  for (int s = 16; s >= 1; s >>= 1) {
    const bool hi = (lane & s) != 0;
#pragma unroll
    for (int i = 0; i < 16; ++i) {
      if (i < s) {
        const float snd = hi ? acc[i] : acc[i + s];
        const float rcv = __shfl_xor_sync(0xffffffffu, snd, s);
        acc[i] = (hi ? acc[i + s] : acc[i]) + rcv;
      }
    }
  }
  g_qpart[blockIdx.y][lane * DH + d] = acc[0];
}

// ---------------------------------------------------------------------------
// Kernel B: warp-autonomous fused scores + online softmax, cp.async pipeline,
// block-level partial merge at the end (4 warps -> 1 partial per block).
// grid (NWARP/4, BB), 128 threads. Warp owns WT=16 timesteps.
// enc_h layout (D, T, B, H): keys[b,t,dir*H+h] = enc_h[((dir*T+t)*B+b)*H+h]
// ---------------------------------------------------------------------------
__global__ __launch_bounds__(128, 3) void attn_main_kernel(
    const float* __restrict__ enc_h, const float* __restrict__ bq) {
  const int b = blockIdx.y;
  const int warp = threadIdx.x >> 5;
  const int lane = threadIdx.x & 31;
  const int widx = blockIdx.x * 4 + warp;   // 0..NWARP-1 within this batch
  const int t0 = widx * WT;

  const float scale = 0.04419417382415922f;  // 1/sqrt(512)

  extern __shared__ float4 ring[];           // [4 warps][SSTAGES][256] = 64KB
  float4* ringw = ring + warp * (SSTAGES * 256);

  // q for this lane in registers: q[p] covers d = p*128 + lane*4
  float4 q[8];
#pragma unroll
  for (int p = 0; p < 8; ++p) {
    const int d = p * 128 + lane * 4;
    const float4 p0 = *(const float4*)(&g_qpart[0][b * DH + d]);
    const float4 p1 = *(const float4*)(&g_qpart[1][b * DH + d]);
    const float4 p2 = *(const float4*)(&g_qpart[2][b * DH + d]);
    const float4 p3 = *(const float4*)(&g_qpart[3][b * DH + d]);
    const float4 bb = *(const float4*)(bq + d);
    q[p].x = p0.x + p1.x + p2.x + p3.x + bb.x;
    q[p].y = p0.y + p1.y + p2.y + p3.y + bb.y;
    q[p].z = p0.z + p1.z + p2.z + p3.z + bb.z;
    q[p].w = p0.w + p1.w + p2.w + p3.w + bb.w;
  }

  float4 a[8];
#pragma unroll
  for (int p = 0; p < 8; ++p) a[p] = make_float4(0.f, 0.f, 0.f, 0.f);
  float m = -1e30f, l = 0.f;

  const size_t tstride = (size_t)BB * HH;          // floats per timestep
  const size_t dirstride = (size_t)TT * BB * HH;   // floats per direction
  const float* base0 = enc_h + ((size_t)t0 * BB + b) * HH + lane * 4;
  const float* base1 = base0 + dirstride;

#define LOAD_STAGE(T)                                                        \
  {                                                                          \
    const int slot_ = (T) & (SSTAGES - 1);                                   \
    const float* r0_ = base0 + (size_t)(T)*tstride;                          \
    const float* r1_ = base1 + (size_t)(T)*tstride;                          \
    float4* d_ = ringw + slot_ * 256 + lane;                                 \
    _Pragma("unroll") for (int p = 0; p < 4; ++p) {                          \
      unsigned sa_ = (unsigned)__cvta_generic_to_shared(d_ + p * 32);        \
      asm volatile("cp.async.cg.shared.global [%0], [%1], 16;" ::"r"(sa_),   \
                   "l"(r0_ + p * 128));                                      \
    }                                                                        \
    _Pragma("unroll") for (int p = 0; p < 4; ++p) {                          \
      unsigned sa_ = (unsigned)__cvta_generic_to_shared(d_ + 128 + p * 32);  \
      asm volatile("cp.async.cg.shared.global [%0], [%1], 16;" ::"r"(sa_),   \
                   "l"(r1_ + p * 128));                                      \
    }                                                                        \
  }

  // prologue: stages 0..PRE-1 in flight (one commit group per stage)
#pragma unroll
  for (int i = 0; i < PRE; ++i) {
    LOAD_STAGE(i)
    asm volatile("cp.async.commit_group;");
  }

#pragma unroll
  for (int i = 0; i < WT; ++i) {
    if (i + PRE < WT) LOAD_STAGE(i + PRE)
    asm volatile("cp.async.commit_group;");  // empty group ok in tail
    asm volatile("cp.async.wait_group %0;" ::"n"(PRE));  // stage i ready

    const float4* kp = ringw + (i & (SSTAGES - 1)) * 256 + lane;
    float4 k[8];
#pragma unroll
    for (int p = 0; p < 8; ++p) k[p] = kp[p * 32];

    float s = 0.f;
#pragma unroll
    for (int p = 0; p < 8; ++p)
      s += q[p].x * k[p].x + q[p].y * k[p].y + q[p].z * k[p].z +
           q[p].w * k[p].w;
#pragma unroll
    for (int off = 16; off >= 1; off >>= 1)
      s += __shfl_xor_sync(0xffffffffu, s, off);
    s *= scale;

    if (lane == 0) g_scores[b * TT + t0 + i] = s;

    if (s > m) {  // warp-uniform branch (s identical on all lanes)
      const float r = __expf(m - s);
#pragma unroll
      for (int p = 0; p < 8; ++p) {
        a[p].x *= r; a[p].y *= r; a[p].z *= r; a[p].w *= r;
      }
      l *= r;
      m = s;
    }
    const float w = __expf(s - m);
    l += w;
#pragma unroll
    for (int p = 0; p < 8; ++p) {
      a[p].x += w * k[p].x;
      a[p].y += w * k[p].y;
      a[p].z += w * k[p].z;
      a[p].w += w * k[p].w;
    }
  }
#undef LOAD_STAGE

  // ---- block-level merge of the 4 warps' partials (reuse ring smem) ----
  asm volatile("cp.async.wait_group 0;" ::: "memory");

  __shared__ float s_m[4], s_l[4];
  if (lane == 0) { s_m[warp] = m; s_l[warp] = l; }
  __syncthreads();

  const float Mb = fmaxf(fmaxf(s_m[0], s_m[1]), fmaxf(s_m[2], s_m[3]));
  const float Lb = s_l[0] * __expf(s_m[0] - Mb) + s_l[1] * __expf(s_m[1] - Mb) +
                   s_l[2] * __expf(s_m[2] - Mb) + s_l[3] * __expf(s_m[3] - Mb);
  const float wf = __expf(m - Mb);  // warp-uniform rescale factor

  // scaled a -> smem: ring[warp*256 + p*32 + lane] covers d = p*128+lane*4
  float4* mw = ring + warp * 256;
#pragma unroll
  for (int p = 0; p < 8; ++p) {
    float4 v = a[p];
    v.x *= wf; v.y *= wf; v.z *= wf; v.w *= wf;
    mw[p * 32 + lane] = v;
  }
  __syncthreads();

  // cooperative sum of 4 warps' vectors -> one partial per block
  float4* pa4 = (float4*)(g_pa + (size_t)(b * NPART + blockIdx.x) * DH);
#pragma unroll
  for (int r = 0; r < 2; ++r) {
    const int idx = r * 128 + threadIdx.x;  // 0..255 float4s
    const float4 v0 = ring[idx];
    const float4 v1 = ring[256 + idx];
    const float4 v2 = ring[512 + idx];
    const float4 v3 = ring[768 + idx];
    float4 v;
    v.x = v0.x + v1.x + v2.x + v3.x;
    v.y = v0.y + v1.y + v2.y + v3.y;
    v.z = v0.z + v1.z + v2.z + v3.z;
    v.w = v0.w + v1.w + v2.w + v3.w;
    pa4[idx] = v;
  }
  if (threadIdx.x == 0) {
    g_pm[b * NPART + blockIdx.x] = Mb;
    g_pl[b * NPART + blockIdx.x] = Lb;
  }
}

// ---------------------------------------------------------------------------
// Kernel C: combine per-block partials -> attn_values + normalized scores.
// grid (BB, 8), 128 threads: block handles 128 d's + 256 score elements.
// ---------------------------------------------------------------------------
__global__ __launch_bounds__(128) void combine_kernel(float* __restrict__ out) {
  const int b = blockIdx.x;
  const int ds = blockIdx.y;
  const int j = threadIdx.x;

  __shared__ float sm[NPART], sw[NPART];
  __shared__ float sL;
  if (j < NPART) sm[j] = g_pm[b * NPART + j];
  __syncthreads();

  float M = -1e30f;
#pragma unroll
  for (int w = 0; w < NPART; ++w) M = fmaxf(M, sm[w]);
  if (j < NPART) sw[j] = __expf(sm[j] - M);
  __syncthreads();

  if (j == 0) {
    float L = 0.f;
#pragma unroll
    for (int w = 0; w < NPART; ++w) L += g_pl[b * NPART + w] * sw[w];
    sL = 1.f / L;
  }
  __syncthreads();
  const float invL = sL;

  const int d = ds * 128 + j;
  const float* pa = g_pa + (size_t)b * NPART * DH + d;
  float v0 = 0.f, v1 = 0.f, v2 = 0.f, v3 = 0.f;
#pragma unroll
  for (int w = 0; w < NPART; w += 4) {
    v0 += sw[w + 0] * pa[(size_t)(w + 0) * DH];
    v1 += sw[w + 1] * pa[(size_t)(w + 1) * DH];
    v2 += sw[w + 2] * pa[(size_t)(w + 2) * DH];
    v3 += sw[w + 3] * pa[(size_t)(w + 3) * DH];
  }
  out[b * DH + d] = (v0 + v1 + v2 + v3) * invL;

  // fused scores normalization: this block covers t in [ds*256, ds*256+256)
  const int tb = ds * 256 + j * 2;
  const float2 s2 = *(const float2*)(g_scores + b * TT + tb);
  float2 o2;
  o2.x = __expf(s2.x - M) * invL;
  o2.y = __expf(s2.y - M) * invL;
  *(float2*)(out + BB * DH + b * TT + tb) = o2;
}

// ---------------------------------------------------------------------------
extern "C" void kernel_launch(void* const* d_in, const int* in_sizes, int n_in,
                              void* d_out, int out_size) {
  const float* input = (const float*)d_in[0];   // (32, 1024)
  const float* enc_h = (const float*)d_in[1];   // (2, 2048, 32, 512)
  // d_in[2] decoder_state: unused
  const float* Wq = (const float*)d_in[3];      // (1024, 1024)
  const float* bq = (const float*)d_in[4];      // (1024,)
  // d_in[5] t: unused
  float* out = (float*)d_out;  // [attn_values (32*1024)] ++ [attn_scores (32*2048)]

  const int smem_bytes = 4 * SSTAGES * 256 * sizeof(float4);  // 64 KB
  cudaFuncSetAttribute(attn_main_kernel,
                       cudaFuncAttributeMaxDynamicSharedMemorySize, smem_bytes);

  qproj_kernel<<<dim3(128, KSPLIT), 256>>>(input, Wq);
  attn_main_kernel<<<dim3(NWARP / 4, BB), 128, smem_bytes>>>(enc_h, bq);
  combine_kernel<<<dim3(BB, 8), 128>>>(out);
}